// round 2
// baseline (speedup 1.0000x reference)
#include <cuda_runtime.h>
#include <cuda_bf16.h>

// Geometry
#define H 512
#define W 512
#define N_ANGLES 512
#define N_DET 736
#define N_SAMP 736

// Plain padded image: support of bilinear is (-1,512) per axis -> pad by 4
#define PAD 4
#define PW (W + 2 * PAD)   // 520
#define PH (H + 2 * PAD)   // 520

// SMEM tile
#define TILE 96
#define TPITCH 97
#define CHUNK 64
#define APB 8              // angles per block (one per warp)

__device__ float g_img[PH * PW];

// ---------------------------------------------------------------------------
__global__ void build_img_kernel(const float* __restrict__ xin,
                                 const float* __restrict__ rin) {
    int idx = blockIdx.x * blockDim.x + threadIdx.x;
    if (idx >= PH * PW) return;
    int yq = idx / PW;
    int xq = idx - yq * PW;
    int y = yq - PAD;
    int x = xq - PAD;
    float v = 0.0f;
    if (y >= 0 && y < H && x >= 0 && x < W)
        v = xin[y * W + x] + rin[y * W + x];
    g_img[idx] = v;
}

__global__ void copy_reco_kernel(const float4* __restrict__ src,
                                 float4* __restrict__ dst, int n4) {
    int i = blockIdx.x * blockDim.x + threadIdx.x;
    if (i < n4) dst[i] = src[i];
}

// interval product [a0,a1] x [b0,b1]
__device__ __forceinline__ void imul(float a0, float a1, float b0, float b1,
                                     float& lo, float& hi) {
    float p1 = a0 * b0, p2 = a0 * b1, p3 = a1 * b0, p4 = a1 * b1;
    lo = fminf(fminf(p1, p2), fminf(p3, p4));
    hi = fmaxf(fmaxf(p1, p2), fmaxf(p3, p4));
}

// ---------------------------------------------------------------------------
// grid = (23, 64). warp -> angle (8 adjacent per block), lane -> detector.
// t-loop chunked by 64; each chunk's image footprint staged into SMEM.
// ---------------------------------------------------------------------------
__global__ void __launch_bounds__(256)
project_kernel(const float* __restrict__ angles, float* __restrict__ sino) {
    __shared__ float tile[TILE * TPITCH];

    const int lane = threadIdx.x & 31;
    const int warp = threadIdx.x >> 5;
    const int a0 = blockIdx.y * APB;
    const int angle = a0 + warp;
    const int d = blockIdx.x * 32 + lane;

    // per-thread ray
    const float theta = __ldg(&angles[angle]);
    float si, c;
    sincosf(theta, &si, &c);
    const float s = (float)d - 367.5f;
    const float CTR = 255.5f + (float)PAD;          // 259.5
    const float BX = s * c + 367.5f * si + CTR;     // px(i) = BX + i*DX
    const float BY = s * si - 367.5f * c + CTR;     // py(i) = BY + i*DY
    const float DX = -si;
    const float DY = c;

    // per-lane active sample range [gi0, gi1) via slab test against support
    float lo = 0.0f, hi = 736.0f;
    if (fabsf(DX) > 1e-6f) {
        float i1 = (3.0f - BX) / DX, i2 = (516.0f - BX) / DX;
        lo = fmaxf(lo, fminf(i1, i2));
        hi = fminf(hi, fmaxf(i1, i2));
    } else if (BX < 3.0f || BX > 516.0f) {
        hi = lo;
    }
    if (fabsf(DY) > 1e-6f) {
        float i1 = (3.0f - BY) / DY, i2 = (516.0f - BY) / DY;
        lo = fmaxf(lo, fminf(i1, i2));
        hi = fminf(hi, fmaxf(i1, i2));
    } else if (BY < 3.0f || BY > 516.0f) {
        hi = lo;
    }
    int gi0 = max(0, (int)floorf(lo) - 1);
    int gi1 = min(736, (int)ceilf(hi) + 2);
    if (gi1 < gi0) gi1 = gi0;

    // block-level cos/sin intervals over the 8-angle range (uniform per block)
    const float tha = __ldg(&angles[a0]);
    const float thb = __ldg(&angles[a0 + APB - 1]);
    float sa, ca, sb, cb;
    sincosf(tha, &sa, &ca);
    sincosf(thb, &sb, &cb);
    float cmin = fminf(ca, cb) - 0.002f;
    float cmax = fmaxf(ca, cb) + 0.002f;
    float smin = fminf(sa, sb) - 0.002f;
    float smax = ((tha <= 1.5707964f) && (thb >= 1.5707963f))
                     ? 1.002f : (fmaxf(sa, sb) + 0.002f);
    const float s0 = (float)(blockIdx.x * 32) - 367.5f;
    const float s1 = s0 + 31.0f;

    float acc = 0.0f;

    for (int ci0 = 0; ci0 < N_SAMP; ci0 += CHUNK) {
        // conservative AABB of block footprint over this chunk (uniform)
        const float t0c = (float)ci0 - 367.5f;
        const float t1c = t0c + (float)(CHUNK - 1);

        float scn, scx, tsn, tsx, ssn, ssx, tcn, tcx;
        imul(s0, s1, cmin, cmax, scn, scx);
        imul(t0c, t1c, smin, smax, tsn, tsx);
        imul(s0, s1, smin, smax, ssn, ssx);
        imul(t0c, t1c, cmin, cmax, tcn, tcx);
        const float pxn = scn - tsx + CTR, pxx = scx - tsn + CTR;
        const float pyn = ssn + tcn + CTR, pyx = ssx + tcx + CTR;

        // skip chunks with no overlap with the support region (uniform branch)
        if (pxx < 2.5f || pxn > 516.5f || pyx < 2.5f || pyn > 516.5f) continue;

        const int tx0 = min(max(__float2int_rd(pxn) - 3, 0), PW - TILE);
        const int ty0 = min(max(__float2int_rd(pyn) - 3, 0), PH - TILE);

        __syncthreads();   // previous chunk's readers done
        // cooperative stage: warp w loads rows w, w+8, ... (96 rows x 96 cols)
        for (int r = warp; r < TILE; r += 8) {
            const float* src = &g_img[(ty0 + r) * PW + tx0];
            float* dst = &tile[r * TPITCH];
            dst[lane]      = __ldg(&src[lane]);
            dst[lane + 32] = __ldg(&src[lane + 32]);
            dst[lane + 64] = __ldg(&src[lane + 64]);
        }
        __syncthreads();

        // per-lane gather over the active sub-range of this chunk
        const int li0 = max(gi0, ci0);
        const int li1 = min(gi1, ci0 + CHUNK);
        float px = (BX - (float)tx0) + (float)li0 * DX;   // tile-local coords
        float py = (BY - (float)ty0) + (float)li0 * DY;

#pragma unroll 2
        for (int i = li0; i < li1; ++i) {
            float xf = floorf(px);
            float yf = floorf(py);
            float fx = px - xf;
            float fy = py - yf;
            int xi = (int)xf;
            int yi = (int)yf;
            // safety clamps (never expected to fire; guarantee determinism)
            xi = min(max(xi, 0), TILE - 2);
            yi = min(max(yi, 0), TILE - 2);
            const float* t0 = &tile[yi * TPITCH + xi];
            float v00 = t0[0];
            float v01 = t0[1];
            float v10 = t0[TPITCH];
            float v11 = t0[TPITCH + 1];
            float top = v00 + fx * (v01 - v00);
            float bot = v10 + fx * (v11 - v10);
            acc += top + fy * (bot - top);
            px += DX;
            py += DY;
        }
    }

    sino[angle * N_DET + d] = acc;   // STEP = 1.0
}

// ---------------------------------------------------------------------------
extern "C" void kernel_launch(void* const* d_in, const int* in_sizes, int n_in,
                              void* d_out, int out_size) {
    const float* xin    = (const float*)d_in[0];   // [1,512,512]
    const float* rin    = (const float*)d_in[1];   // [1,512,512]
    const float* angles = (const float*)d_in[2];   // [512]

    float* out = (float*)d_out;
    float* sino_out = out;                         // [1,512,736]
    float* reco_out = out + N_ANGLES * N_DET;      // [1,512,512]

    {
        int total = PH * PW;
        int threads = 256;
        int blocks = (total + threads - 1) / threads;
        build_img_kernel<<<blocks, threads>>>(xin, rin);
    }
    {
        int n4 = (H * W) / 4;
        int threads = 256;
        int blocks = (n4 + threads - 1) / threads;
        copy_reco_kernel<<<blocks, threads>>>((const float4*)rin, (float4*)reco_out, n4);
    }
    {
        dim3 grid(N_DET / 32, N_ANGLES / APB);     // (23, 64)
        project_kernel<<<grid, 256>>>(angles, sino_out);
    }
}

// round 3
// speedup vs baseline: 1.4110x; 1.4110x over previous
#include <cuda_runtime.h>
#include <cuda_bf16.h>

// Geometry
#define H 512
#define W 512
#define N_ANGLES 512
#define N_DET 736
#define N_SAMP 736

// Full-range padding: sample coords span [-264.3, 775.3] -> pad 272 each side.
// All taps for any sample index are in-bounds; outside-support taps read 0.
#define PAD 272
#define PW (W + 2 * PAD)   // 1056
#define PH (H + 2 * PAD)   // 1056

// Pair image: g_img2[y][x] = (I[y][x], I[y][x+1]) on the zero-padded field.
__device__ float2 g_img2[PH * PW];

// ---------------------------------------------------------------------------
__global__ void build_img2_kernel(const float* __restrict__ xin,
                                  const float* __restrict__ rin) {
    int idx = blockIdx.x * blockDim.x + threadIdx.x;
    if (idx >= PH * PW) return;
    int yq = idx / PW;
    int xq = idx - yq * PW;
    int y = yq - PAD;
    int x = xq - PAD;

    float2 q = make_float2(0.0f, 0.0f);
    if (y >= 0 && y < H) {
        if (x >= 0 && x < W)
            q.x = xin[y * W + x] + rin[y * W + x];
        int x1 = x + 1;
        if (x1 >= 0 && x1 < W)
            q.y = xin[y * W + x1] + rin[y * W + x1];
    }
    g_img2[idx] = q;
}

__global__ void copy_reco_kernel(const float4* __restrict__ src,
                                 float4* __restrict__ dst, int n4) {
    int i = blockIdx.x * blockDim.x + threadIdx.x;
    if (i < n4) dst[i] = src[i];
}

// ---------------------------------------------------------------------------
// grid = (23, 512): blockIdx.y = angle, blockIdx.x = 32-detector block.
// block = 256 = 8 warps; each warp: 4 detectors x 8 t-phases.
// lane = tq*4 + dq. Lane samples t-index n = 8*it + tq, it in [wit0, wit1).
// ---------------------------------------------------------------------------
__global__ void __launch_bounds__(256, 6)
project_kernel(const float* __restrict__ angles, float* __restrict__ sino) {
    const int lane = threadIdx.x & 31;
    const int warp = threadIdx.x >> 5;
    const int tq = lane >> 2;    // 0..7
    const int dq = lane & 3;     // 0..3

    const int angle = blockIdx.y;
    const int d = blockIdx.x * 32 + warp * 4 + dq;

    const float theta = __ldg(&angles[angle]);
    float si, c;
    sincosf(theta, &si, &c);

    const float s = (float)d - 367.5f;
    const float CTR = 255.5f + (float)PAD;        // 527.5

    // px(n) = s*c - (n - 367.5)*si + CTR, n = 8*it + tq
    const float BX = s * c + (367.5f - (float)tq) * si + CTR;
    const float BY = s * si - (367.5f - (float)tq) * c + CTR;
    const float DX = -8.0f * si;
    const float DY = 8.0f * c;

    // ---- exact chord clipping (unpadded coords), per lane ----
    // px = A - t*si,  py = B + t*c,  support (-1, 512) each axis
    const float A = s * c + 255.5f;
    const float B = s * si + 255.5f;
    float tlo = -368.0f, thi = 368.0f;
    if (fabsf(si) > 1e-6f) {
        float u1 = (A - 512.0f) / si, u2 = (A + 1.0f) / si;
        tlo = fmaxf(tlo, fminf(u1, u2));
        thi = fminf(thi, fmaxf(u1, u2));
    } else if (A <= -1.0f || A >= 512.0f) {
        thi = tlo;
    }
    if (fabsf(c) > 1e-6f) {
        float u1 = (-1.0f - B) / c, u2 = (512.0f - B) / c;
        tlo = fmaxf(tlo, fminf(u1, u2));
        thi = fminf(thi, fmaxf(u1, u2));
    } else if (B <= -1.0f || B >= 512.0f) {
        thi = tlo;
    }
    // lane's it-range; floor/ceil slack is safe (padding is zero)
    int it0 = __float2int_rd((tlo + 367.5f - (float)tq) * 0.125f);
    int it1 = __float2int_ru((thi + 367.5f - (float)tq) * 0.125f) + 1;
    it0 = min(max(it0, 0), N_SAMP / 8);
    it1 = min(max(it1, it0), N_SAMP / 8);

    const int wit0 = __reduce_min_sync(0xFFFFFFFFu, it0);
    const int wit1 = __reduce_max_sync(0xFFFFFFFFu, it1);

    float px = BX + (float)wit0 * DX;
    float py = BY + (float)wit0 * DY;
    float acc = 0.0f;

#pragma unroll 4
    for (int it = wit0; it < wit1; ++it) {
        const float xf = floorf(px);
        const float yf = floorf(py);
        const float fx = px - xf;
        const float fy = py - yf;
        const int idx = (int)yf * PW + (int)xf;
        const float2 q0 = __ldg(&g_img2[idx]);        // (v00, v01)
        const float2 q1 = __ldg(&g_img2[idx + PW]);   // (v10, v11)
        const float top = fmaf(fx, q0.y - q0.x, q0.x);
        const float bot = fmaf(fx, q1.y - q1.x, q1.x);
        acc = fmaf(fy, bot - top, acc + top);
        px += DX;
        py += DY;
    }

    // reduce over tq (lanes separated by multiples of 4)
    acc += __shfl_xor_sync(0xFFFFFFFFu, acc, 16);
    acc += __shfl_xor_sync(0xFFFFFFFFu, acc, 8);
    acc += __shfl_xor_sync(0xFFFFFFFFu, acc, 4);

    if (tq == 0) {
        sino[angle * N_DET + d] = acc;   // STEP = 1.0
    }
}

// ---------------------------------------------------------------------------
extern "C" void kernel_launch(void* const* d_in, const int* in_sizes, int n_in,
                              void* d_out, int out_size) {
    const float* xin    = (const float*)d_in[0];   // [1,512,512]
    const float* rin    = (const float*)d_in[1];   // [1,512,512]
    const float* angles = (const float*)d_in[2];   // [512]

    float* out = (float*)d_out;
    float* sino_out = out;                         // [1,512,736]
    float* reco_out = out + N_ANGLES * N_DET;      // [1,512,512]

    {
        int total = PH * PW;
        int threads = 256;
        int blocks = (total + threads - 1) / threads;
        build_img2_kernel<<<blocks, threads>>>(xin, rin);
    }
    {
        int n4 = (H * W) / 4;
        int threads = 256;
        int blocks = (n4 + threads - 1) / threads;
        copy_reco_kernel<<<blocks, threads>>>((const float4*)rin, (float4*)reco_out, n4);
    }
    {
        dim3 grid(N_DET / 32, N_ANGLES);           // (23, 512)
        project_kernel<<<grid, 256>>>(angles, sino_out);
    }
}

// round 4
// speedup vs baseline: 1.6756x; 1.1875x over previous
#include <cuda_runtime.h>
#include <cuda_bf16.h>
#include <cuda_fp16.h>

// Geometry
#define H 512
#define W 512
#define N_ANGLES 512
#define N_DET 736
#define N_SAMP 736

// Full-range padding: sample coords span ~[-520,520] about center -> pad 272.
// Every tap for every sample index is in-bounds; outside-support taps read 0.
#define PAD 272
#define PW (W + 2 * PAD)   // 1056
#define PH (H + 2 * PAD)   // 1056

// fp16 quad image: 8 bytes per pixel =
//   .x = half2( I[y][x],   I[y][x+1]   )
//   .y = half2( I[y+1][x], I[y+1][x+1] )
__device__ uint2 g_quadh[PH * PW];

// ---------------------------------------------------------------------------
__global__ void build_quadh_kernel(const float* __restrict__ xin,
                                   const float* __restrict__ rin) {
    int idx = blockIdx.x * blockDim.x + threadIdx.x;
    if (idx >= PH * PW) return;
    int yq = idx / PW;
    int xq = idx - yq * PW;
    int y = yq - PAD;
    int x = xq - PAD;

    float v00 = 0.f, v01 = 0.f, v10 = 0.f, v11 = 0.f;
    if (y >= 0 && y < H) {
        if (x >= 0 && x < W)     v00 = xin[y * W + x]     + rin[y * W + x];
        if (x + 1 >= 0 && x + 1 < W) v01 = xin[y * W + x + 1] + rin[y * W + x + 1];
    }
    if (y + 1 >= 0 && y + 1 < H) {
        int y1 = y + 1;
        if (x >= 0 && x < W)     v10 = xin[y1 * W + x]     + rin[y1 * W + x];
        if (x + 1 >= 0 && x + 1 < W) v11 = xin[y1 * W + x + 1] + rin[y1 * W + x + 1];
    }

    __half2 h0 = __floats2half2_rn(v00, v01);
    __half2 h1 = __floats2half2_rn(v10, v11);
    uint2 q;
    q.x = *reinterpret_cast<unsigned int*>(&h0);
    q.y = *reinterpret_cast<unsigned int*>(&h1);
    g_quadh[idx] = q;
}

__global__ void copy_reco_kernel(const float4* __restrict__ src,
                                 float4* __restrict__ dst, int n4) {
    int i = blockIdx.x * blockDim.x + threadIdx.x;
    if (i < n4) dst[i] = src[i];
}

// ---------------------------------------------------------------------------
// grid = (23, 512): blockIdx.y = angle, blockIdx.x = 32-detector block.
// block = 256 = 8 warps; each warp: 4 detectors x 8 t-phases.
// lane = tq*4 + dq. Lane samples t-index n = 8*it + tq, it in [wit0, wit1).
// ---------------------------------------------------------------------------
__global__ void __launch_bounds__(256, 6)
project_kernel(const float* __restrict__ angles, float* __restrict__ sino) {
    const int lane = threadIdx.x & 31;
    const int warp = threadIdx.x >> 5;
    const int tq = lane >> 2;    // 0..7
    const int dq = lane & 3;     // 0..3

    const int angle = blockIdx.y;
    const int d = blockIdx.x * 32 + warp * 4 + dq;

    const float theta = __ldg(&angles[angle]);
    float si, c;
    sincosf(theta, &si, &c);

    const float s = (float)d - 367.5f;
    const float CTR = 255.5f + (float)PAD;        // 527.5

    // px(n) = s*c - (n - 367.5)*si + CTR, n = 8*it + tq
    const float BX = s * c + (367.5f - (float)tq) * si + CTR;
    const float BY = s * si - (367.5f - (float)tq) * c + CTR;
    const float DX = -8.0f * si;
    const float DY = 8.0f * c;

    // ---- exact chord clipping (unpadded coords), per lane ----
    // px = A - t*si,  py = B + t*c,  support (-1, 512) each axis
    const float A = s * c + 255.5f;
    const float B = s * si + 255.5f;
    float tlo = -368.0f, thi = 368.0f;
    if (fabsf(si) > 1e-6f) {
        float u1 = (A - 512.0f) / si, u2 = (A + 1.0f) / si;
        tlo = fmaxf(tlo, fminf(u1, u2));
        thi = fminf(thi, fmaxf(u1, u2));
    } else if (A <= -1.0f || A >= 512.0f) {
        thi = tlo;
    }
    if (fabsf(c) > 1e-6f) {
        float u1 = (-1.0f - B) / c, u2 = (512.0f - B) / c;
        tlo = fmaxf(tlo, fminf(u1, u2));
        thi = fminf(thi, fmaxf(u1, u2));
    } else if (B <= -1.0f || B >= 512.0f) {
        thi = tlo;
    }
    // lane's it-range; floor/ceil slack is safe (padding is zero)
    int it0 = __float2int_rd((tlo + 367.5f - (float)tq) * 0.125f);
    int it1 = __float2int_ru((thi + 367.5f - (float)tq) * 0.125f) + 1;
    it0 = min(max(it0, 0), N_SAMP / 8);
    it1 = min(max(it1, it0), N_SAMP / 8);

    const int wit0 = __reduce_min_sync(0xFFFFFFFFu, it0);
    const int wit1 = __reduce_max_sync(0xFFFFFFFFu, it1);

    float px = BX + (float)wit0 * DX;
    float py = BY + (float)wit0 * DY;
    float acc = 0.0f;

#pragma unroll 4
    for (int it = wit0; it < wit1; ++it) {
        const int xi = __float2int_rd(px);       // coords are always positive
        const int yi = __float2int_rd(py);
        const float fx = px - (float)xi;
        const float fy = py - (float)yi;
        const uint2 q = __ldg(&g_quadh[yi * PW + xi]);
        const __half2 h0 = *reinterpret_cast<const __half2*>(&q.x);
        const __half2 h1 = *reinterpret_cast<const __half2*>(&q.y);
        const float2 f0 = __half22float2(h0);    // (v00, v01)
        const float2 f1 = __half22float2(h1);    // (v10, v11)
        const float top = fmaf(fx, f0.y - f0.x, f0.x);
        const float bot = fmaf(fx, f1.y - f1.x, f1.x);
        acc = fmaf(fy, bot - top, acc + top);
        px += DX;
        py += DY;
    }

    // reduce over tq (lanes separated by multiples of 4)
    acc += __shfl_xor_sync(0xFFFFFFFFu, acc, 16);
    acc += __shfl_xor_sync(0xFFFFFFFFu, acc, 8);
    acc += __shfl_xor_sync(0xFFFFFFFFu, acc, 4);

    if (tq == 0) {
        sino[angle * N_DET + d] = acc;   // STEP = 1.0
    }
}

// ---------------------------------------------------------------------------
extern "C" void kernel_launch(void* const* d_in, const int* in_sizes, int n_in,
                              void* d_out, int out_size) {
    const float* xin    = (const float*)d_in[0];   // [1,512,512]
    const float* rin    = (const float*)d_in[1];   // [1,512,512]
    const float* angles = (const float*)d_in[2];   // [512]

    float* out = (float*)d_out;
    float* sino_out = out;                         // [1,512,736]
    float* reco_out = out + N_ANGLES * N_DET;      // [1,512,512]

    {
        int total = PH * PW;
        int threads = 256;
        int blocks = (total + threads - 1) / threads;
        build_quadh_kernel<<<blocks, threads>>>(xin, rin);
    }
    {
        int n4 = (H * W) / 4;
        int threads = 256;
        int blocks = (n4 + threads - 1) / threads;
        copy_reco_kernel<<<blocks, threads>>>((const float4*)rin, (float4*)reco_out, n4);
    }
    {
        dim3 grid(N_DET / 32, N_ANGLES);           // (23, 512)
        project_kernel<<<grid, 256>>>(angles, sino_out);
    }
}

// round 7
// speedup vs baseline: 2.8417x; 1.6960x over previous
#include <cuda_runtime.h>
#include <cuda_bf16.h>
#include <cuda_fp16.h>

// Geometry
#define H 512
#define W 512
#define N_ANGLES 512
#define N_DET 736
#define N_SAMP 736

// Full-range padding: sample coords span ~[-520,520] about center -> pad 272.
#define PAD 272
#define PW (W + 2 * PAD)   // 1056 (divisible by 4)
#define PH (H + 2 * PAD)   // 1056
#define TW (PW / 4)        // 264 tiles per row

// fp16 quad image in 4x4-pixel tiled layout.
// Element (8B) at pixel (y,x):  tile = (y>>2, x>>2), intra = (y&3, x&3)
// linear elem index = ((y>>2)*TW + (x>>2))*16 + (y&3)*4 + (x&3)
// One 128B line == one 4x4 pixel block.
__device__ uint2 g_quadh[PH * PW];

__device__ __forceinline__ int tiled_idx(int y, int x) {
    return (((y >> 2) * TW + (x >> 2)) << 4) + ((y & 3) << 2) + (x & 3);
}

// ---------------------------------------------------------------------------
__global__ void build_quadh_kernel(const float* __restrict__ xin,
                                   const float* __restrict__ rin) {
    int idx = blockIdx.x * blockDim.x + threadIdx.x;
    if (idx >= PH * PW) return;
    int yq = idx / PW;
    int xq = idx - yq * PW;
    int y = yq - PAD;
    int x = xq - PAD;

    float v00 = 0.f, v01 = 0.f, v10 = 0.f, v11 = 0.f;
    if (y >= 0 && y < H) {
        if (x >= 0 && x < W)         v00 = xin[y * W + x]     + rin[y * W + x];
        if (x + 1 >= 0 && x + 1 < W) v01 = xin[y * W + x + 1] + rin[y * W + x + 1];
    }
    if (y + 1 >= 0 && y + 1 < H) {
        int y1 = y + 1;
        if (x >= 0 && x < W)         v10 = xin[y1 * W + x]     + rin[y1 * W + x];
        if (x + 1 >= 0 && x + 1 < W) v11 = xin[y1 * W + x + 1] + rin[y1 * W + x + 1];
    }

    __half2 h0 = __floats2half2_rn(v00, v01);
    __half2 h1 = __floats2half2_rn(v10, v11);
    uint2 q;
    q.x = *reinterpret_cast<unsigned int*>(&h0);
    q.y = *reinterpret_cast<unsigned int*>(&h1);
    g_quadh[tiled_idx(yq, xq)] = q;
}

__global__ void copy_reco_kernel(const float4* __restrict__ src,
                                 float4* __restrict__ dst, int n4) {
    int i = blockIdx.x * blockDim.x + threadIdx.x;
    if (i < n4) dst[i] = src[i];
}

// ---------------------------------------------------------------------------
// grid = (23, 512): blockIdx.y = angle, blockIdx.x = 32-detector block.
// block = 256 = 8 warps; each warp: 4 detectors x 8 t-phases.
// lane = tq*4 + dq. Lane samples t-index n = 8*it + tq, it in [wit0, wit1).
// ---------------------------------------------------------------------------
__global__ void __launch_bounds__(256, 6)
project_kernel(const float* __restrict__ angles, float* __restrict__ sino) {
    const int lane = threadIdx.x & 31;
    const int warp = threadIdx.x >> 5;
    const int tq = lane >> 2;    // 0..7
    const int dq = lane & 3;     // 0..3

    const int angle = blockIdx.y;
    const int d = blockIdx.x * 32 + warp * 4 + dq;

    const float theta = __ldg(&angles[angle]);
    float si, c;
    sincosf(theta, &si, &c);

    const float s = (float)d - 367.5f;
    const float CTR = 255.5f + (float)PAD;        // 527.5

    // px(n) = s*c - (n - 367.5)*si + CTR, n = 8*it + tq
    const float BX = s * c + (367.5f - (float)tq) * si + CTR;
    const float BY = s * si - (367.5f - (float)tq) * c + CTR;
    const float DX = -8.0f * si;
    const float DY = 8.0f * c;

    // ---- exact chord clipping (unpadded coords), per lane ----
    const float A = s * c + 255.5f;
    const float B = s * si + 255.5f;
    float tlo = -368.0f, thi = 368.0f;
    if (fabsf(si) > 1e-6f) {
        float u1 = (A - 512.0f) / si, u2 = (A + 1.0f) / si;
        tlo = fmaxf(tlo, fminf(u1, u2));
        thi = fminf(thi, fmaxf(u1, u2));
    } else if (A <= -1.0f || A >= 512.0f) {
        thi = tlo;
    }
    if (fabsf(c) > 1e-6f) {
        float u1 = (-1.0f - B) / c, u2 = (512.0f - B) / c;
        tlo = fmaxf(tlo, fminf(u1, u2));
        thi = fminf(thi, fmaxf(u1, u2));
    } else if (B <= -1.0f || B >= 512.0f) {
        thi = tlo;
    }
    int it0 = __float2int_rd((tlo + 367.5f - (float)tq) * 0.125f);
    int it1 = __float2int_ru((thi + 367.5f - (float)tq) * 0.125f) + 1;
    it0 = min(max(it0, 0), N_SAMP / 8);
    it1 = min(max(it1, it0), N_SAMP / 8);

    const int wit0 = __reduce_min_sync(0xFFFFFFFFu, it0);
    const int wit1 = __reduce_max_sync(0xFFFFFFFFu, it1);

    float px = BX + (float)wit0 * DX;
    float py = BY + (float)wit0 * DY;
    float acc = 0.0f;

#pragma unroll 4
    for (int it = wit0; it < wit1; ++it) {
        const int xi = __float2int_rd(px);       // coords always positive
        const int yi = __float2int_rd(py);
        const float fx = px - (float)xi;
        const float fy = py - (float)yi;
        const int idx = (((yi >> 2) * TW + (xi >> 2)) << 4)
                        + ((yi & 3) << 2) + (xi & 3);
        const uint2 q = __ldg(&g_quadh[idx]);
        const __half2 h0 = *reinterpret_cast<const __half2*>(&q.x);
        const __half2 h1 = *reinterpret_cast<const __half2*>(&q.y);
        const float2 f0 = __half22float2(h0);    // (v00, v01)
        const float2 f1 = __half22float2(h1);    // (v10, v11)
        const float top = fmaf(fx, f0.y - f0.x, f0.x);
        const float bot = fmaf(fx, f1.y - f1.x, f1.x);
        acc = fmaf(fy, bot - top, acc + top);
        px += DX;
        py += DY;
    }

    // reduce over tq (lanes separated by multiples of 4)
    acc += __shfl_xor_sync(0xFFFFFFFFu, acc, 16);
    acc += __shfl_xor_sync(0xFFFFFFFFu, acc, 8);
    acc += __shfl_xor_sync(0xFFFFFFFFu, acc, 4);

    if (tq == 0) {
        sino[angle * N_DET + d] = acc;   // STEP = 1.0
    }
}

// ---------------------------------------------------------------------------
extern "C" void kernel_launch(void* const* d_in, const int* in_sizes, int n_in,
                              void* d_out, int out_size) {
    const float* xin    = (const float*)d_in[0];   // [1,512,512]
    const float* rin    = (const float*)d_in[1];   // [1,512,512]
    const float* angles = (const float*)d_in[2];   // [512]

    float* out = (float*)d_out;
    float* sino_out = out;                         // [1,512,736]
    float* reco_out = out + N_ANGLES * N_DET;      // [1,512,512]

    {
        int total = PH * PW;
        int threads = 256;
        int blocks = (total + threads - 1) / threads;
        build_quadh_kernel<<<blocks, threads>>>(xin, rin);
    }
    {
        int n4 = (H * W) / 4;
        int threads = 256;
        int blocks = (n4 + threads - 1) / threads;
        copy_reco_kernel<<<blocks, threads>>>((const float4*)rin, (float4*)reco_out, n4);
    }
    {
        dim3 grid(N_DET / 32, N_ANGLES);           // (23, 512)
        project_kernel<<<grid, 256>>>(angles, sino_out);
    }
}

// round 8
// speedup vs baseline: 2.9108x; 1.0243x over previous
#include <cuda_runtime.h>
#include <cuda_bf16.h>
#include <cuda_fp16.h>

// Geometry
#define H 512
#define W 512
#define N_ANGLES 512
#define N_DET 736
#define N_SAMP 736

// Full-range padding: sample coords span ~[-520,520] about center -> pad 272.
#define PAD 272
#define PW (W + 2 * PAD)   // 1056 (divisible by 4)
#define PH (H + 2 * PAD)   // 1056
#define TW (PW / 4)        // 264 tiles per row

// fp16 quad image in 4x4-pixel tiled layout (one 128B line == 4x4 px block).
//   .x = half2( I[y][x],   I[y][x+1]   )
//   .y = half2( I[y+1][x], I[y+1][x+1] )
__device__ uint2 g_quadh[PH * PW];

__device__ __forceinline__ int tiled_idx(int y, int x) {
    return (((y >> 2) * TW + (x >> 2)) << 4) + ((y & 3) << 2) + (x & 3);
}

// ---------------------------------------------------------------------------
__global__ void build_quadh_kernel(const float* __restrict__ xin,
                                   const float* __restrict__ rin) {
    int idx = blockIdx.x * blockDim.x + threadIdx.x;
    if (idx >= PH * PW) return;
    int yq = idx / PW;
    int xq = idx - yq * PW;
    int y = yq - PAD;
    int x = xq - PAD;

    float v00 = 0.f, v01 = 0.f, v10 = 0.f, v11 = 0.f;
    if (y >= 0 && y < H) {
        if (x >= 0 && x < W)         v00 = xin[y * W + x]     + rin[y * W + x];
        if (x + 1 >= 0 && x + 1 < W) v01 = xin[y * W + x + 1] + rin[y * W + x + 1];
    }
    if (y + 1 >= 0 && y + 1 < H) {
        int y1 = y + 1;
        if (x >= 0 && x < W)         v10 = xin[y1 * W + x]     + rin[y1 * W + x];
        if (x + 1 >= 0 && x + 1 < W) v11 = xin[y1 * W + x + 1] + rin[y1 * W + x + 1];
    }

    __half2 h0 = __floats2half2_rn(v00, v01);
    __half2 h1 = __floats2half2_rn(v10, v11);
    uint2 q;
    q.x = *reinterpret_cast<unsigned int*>(&h0);
    q.y = *reinterpret_cast<unsigned int*>(&h1);
    g_quadh[tiled_idx(yq, xq)] = q;
}

__global__ void copy_reco_kernel(const float4* __restrict__ src,
                                 float4* __restrict__ dst, int n4) {
    int i = blockIdx.x * blockDim.x + threadIdx.x;
    if (i < n4) dst[i] = src[i];
}

// ---------------------------------------------------------------------------
// grid = (23, 256): blockIdx.y = angle PAIR, blockIdx.x = 32-detector block.
// block = 256 = 8 warps; each warp: 2 angles x 4 detectors x 4 t-phases.
// lane = aq*16 + tq*4 + dq. Lane samples t-index n = 4*it + tq.
// ---------------------------------------------------------------------------
__global__ void __launch_bounds__(256, 6)
project_kernel(const float* __restrict__ angles, float* __restrict__ sino) {
    const int lane = threadIdx.x & 31;
    const int warp = threadIdx.x >> 5;
    const int aq = lane >> 4;          // 0..1
    const int tq = (lane >> 2) & 3;    // 0..3
    const int dq = lane & 3;           // 0..3

    const int angle = blockIdx.y * 2 + aq;
    const int d = blockIdx.x * 32 + warp * 4 + dq;

    const float theta = __ldg(&angles[angle]);
    float si, c;
    sincosf(theta, &si, &c);

    const float s = (float)d - 367.5f;
    const float CTR = 255.5f + (float)PAD;        // 527.5

    // px(n) = s*c - (n - 367.5)*si + CTR, n = 4*it + tq
    const float BX = s * c + (367.5f - (float)tq) * si + CTR;
    const float BY = s * si - (367.5f - (float)tq) * c + CTR;
    const float DX = -4.0f * si;
    const float DY = 4.0f * c;

    // ---- exact chord clipping (unpadded coords), per lane ----
    const float A = s * c + 255.5f;
    const float B = s * si + 255.5f;
    float tlo = -368.0f, thi = 368.0f;
    if (fabsf(si) > 1e-6f) {
        float u1 = (A - 512.0f) / si, u2 = (A + 1.0f) / si;
        tlo = fmaxf(tlo, fminf(u1, u2));
        thi = fminf(thi, fmaxf(u1, u2));
    } else if (A <= -1.0f || A >= 512.0f) {
        thi = tlo;
    }
    if (fabsf(c) > 1e-6f) {
        float u1 = (-1.0f - B) / c, u2 = (512.0f - B) / c;
        tlo = fmaxf(tlo, fminf(u1, u2));
        thi = fminf(thi, fmaxf(u1, u2));
    } else if (B <= -1.0f || B >= 512.0f) {
        thi = tlo;
    }
    // lane's it-range (n = 4*it + tq); floor/ceil slack safe (padding is zero)
    int it0 = __float2int_rd((tlo + 367.5f - (float)tq) * 0.25f);
    int it1 = __float2int_ru((thi + 367.5f - (float)tq) * 0.25f) + 1;
    it0 = min(max(it0, 0), N_SAMP / 4);
    it1 = min(max(it1, it0), N_SAMP / 4);

    const int wit0 = __reduce_min_sync(0xFFFFFFFFu, it0);
    const int wit1 = __reduce_max_sync(0xFFFFFFFFu, it1);

    float px = BX + (float)wit0 * DX;
    float py = BY + (float)wit0 * DY;
    float acc = 0.0f;

#pragma unroll 4
    for (int it = wit0; it < wit1; ++it) {
        const int xi = __float2int_rd(px);       // coords always positive
        const int yi = __float2int_rd(py);
        const float fx = px - (float)xi;
        const float fy = py - (float)yi;
        const int idx = (((yi >> 2) * TW + (xi >> 2)) << 4)
                        + ((yi & 3) << 2) + (xi & 3);
        const uint2 q = __ldg(&g_quadh[idx]);
        const __half2 h0 = *reinterpret_cast<const __half2*>(&q.x);
        const __half2 h1 = *reinterpret_cast<const __half2*>(&q.y);
        const float2 f0 = __half22float2(h0);    // (v00, v01)
        const float2 f1 = __half22float2(h1);    // (v10, v11)
        const float top = fmaf(fx, f0.y - f0.x, f0.x);
        const float bot = fmaf(fx, f1.y - f1.x, f1.x);
        acc = fmaf(fy, bot - top, acc + top);
        px += DX;
        py += DY;
    }

    // reduce over tq (lanes differing in bits [2:3])
    acc += __shfl_xor_sync(0xFFFFFFFFu, acc, 8);
    acc += __shfl_xor_sync(0xFFFFFFFFu, acc, 4);

    if (tq == 0) {
        sino[angle * N_DET + d] = acc;   // STEP = 1.0
    }
}

// ---------------------------------------------------------------------------
extern "C" void kernel_launch(void* const* d_in, const int* in_sizes, int n_in,
                              void* d_out, int out_size) {
    const float* xin    = (const float*)d_in[0];   // [1,512,512]
    const float* rin    = (const float*)d_in[1];   // [1,512,512]
    const float* angles = (const float*)d_in[2];   // [512]

    float* out = (float*)d_out;
    float* sino_out = out;                         // [1,512,736]
    float* reco_out = out + N_ANGLES * N_DET;      // [1,512,512]

    {
        int total = PH * PW;
        int threads = 256;
        int blocks = (total + threads - 1) / threads;
        build_quadh_kernel<<<blocks, threads>>>(xin, rin);
    }
    {
        int n4 = (H * W) / 4;
        int threads = 256;
        int blocks = (n4 + threads - 1) / threads;
        copy_reco_kernel<<<blocks, threads>>>((const float4*)rin, (float4*)reco_out, n4);
    }
    {
        dim3 grid(N_DET / 32, N_ANGLES / 2);       // (23, 256)
        project_kernel<<<grid, 256>>>(angles, sino_out);
    }
}